// round 11
// baseline (speedup 1.0000x reference)
#include <cuda_runtime.h>
#include <math.h>
#include <stdint.h>

// Problem dims
#define BB 32
#define TT 512
#define II 128
#define HH 512
#define OO 128

// ---------------- device scratch (no allocs allowed) ----------------
__device__ float    g_pre [TT * HH * BB];   // [T][H][B] (reused pre0/pre1)
__device__ float    g_traj[TT * HH * BB];   // [T][H][B] (h1, then reused as h2)
__device__ float    g_tmp [TT * OO * BB];   // [T][O][B] (fc pre-transpose)
__device__ float    g_hping[4 * HH * BB];   // 2 ping-pong pairs (layer0, layer1)
__device__ unsigned g_counters[1024];       // per-step barrier counters (512 per layer)

// ---------------- init: zero counters + h0 buffers each replay ----------------
__global__ void init_kernel(unsigned* counters, float* hping) {
    int i = blockIdx.x * blockDim.x + threadIdx.x;
    int stride = gridDim.x * blockDim.x;
    for (int e = i; e < 1024; e += stride) counters[e] = 0u;
    for (int e = i; e < 4 * HH * BB; e += stride) hping[e] = 0.0f;
}

// ---------------- fp32 GEMM: C[t][j][b] = bias(j) + sum_k A(t,k,b)*W[j][k] ----------------
// grid: (N/128, T/2), block: 256. Tile 128j x 64n, microtile 8j x 4n. (R4-proven)
__global__ void __launch_bounds__(256)
gemm_pre_kernel(const float* __restrict__ A, const float* __restrict__ W,
                const float* __restrict__ bias1, const float* __restrict__ bias2,
                float* __restrict__ C,
                int K, long sAt, long sAk, long sAb, int N)
{
    __shared__ float Ws[32][132];  // [k][j] padded (128 j)
    __shared__ float As[32][68];   // [k][n] padded (64 n)

    const int t0  = blockIdx.y * 2;
    const int j0  = blockIdx.x * 128;
    const int tid = threadIdx.x;
    const int jg  = tid >> 4;      // 0..15 (8 j each)
    const int ng  = tid & 15;      // 0..15 (4 n each)

    float acc[8][4];
#pragma unroll
    for (int a = 0; a < 8; a++)
#pragma unroll
        for (int b = 0; b < 4; b++) acc[a][b] = 0.0f;

    for (int kt = 0; kt < K; kt += 32) {
        __syncthreads();
        {
            const int rowb = tid >> 3;
            const int k4   = (tid & 7) * 4;
#pragma unroll
            for (int i = 0; i < 4; i++) {
                const int row = i * 32 + rowb;
                float4 v = *(const float4*)&W[(size_t)(j0 + row) * K + kt + k4];
                Ws[k4 + 0][row] = v.x;
                Ws[k4 + 1][row] = v.y;
                Ws[k4 + 2][row] = v.z;
                Ws[k4 + 3][row] = v.w;
            }
        }
        if (sAb == 1) {   // b-contiguous (trajectory layout [t][k][b])
#pragma unroll
            for (int i = 0; i < 2; i++) {
                int f = tid + i * 256;
                int k  = f >> 4;
                int nq = (f & 15) * 4;
                int tloc = nq >> 5, b4 = nq & 31;
                float4 v = *(const float4*)&A[(size_t)(t0 + tloc) * sAt +
                                              (size_t)(kt + k) * sAk + b4];
                *(float4*)&As[k][nq] = v;
            }
        } else {          // k-contiguous (inputs layout [b][t][i])
#pragma unroll
            for (int i = 0; i < 2; i++) {
                int f = tid + i * 256;
                int n  = f >> 3;
                int kq = (f & 7) * 4;
                int tloc = n >> 5, b = n & 31;
                float4 v = *(const float4*)&A[(size_t)b * sAb +
                                              (size_t)(t0 + tloc) * sAt + kt + kq];
                As[kq + 0][n] = v.x;
                As[kq + 1][n] = v.y;
                As[kq + 2][n] = v.z;
                As[kq + 3][n] = v.w;
            }
        }
        __syncthreads();
#pragma unroll
        for (int k = 0; k < 32; k++) {
            const float4 w0 = *(const float4*)&Ws[k][jg * 8];
            const float4 w1 = *(const float4*)&Ws[k][jg * 8 + 4];
            const float4 a  = *(const float4*)&As[k][ng * 4];
            acc[0][0] += w0.x * a.x; acc[0][1] += w0.x * a.y; acc[0][2] += w0.x * a.z; acc[0][3] += w0.x * a.w;
            acc[1][0] += w0.y * a.x; acc[1][1] += w0.y * a.y; acc[1][2] += w0.y * a.z; acc[1][3] += w0.y * a.w;
            acc[2][0] += w0.z * a.x; acc[2][1] += w0.z * a.y; acc[2][2] += w0.z * a.z; acc[2][3] += w0.z * a.w;
            acc[3][0] += w0.w * a.x; acc[3][1] += w0.w * a.y; acc[3][2] += w0.w * a.z; acc[3][3] += w0.w * a.w;
            acc[4][0] += w1.x * a.x; acc[4][1] += w1.x * a.y; acc[4][2] += w1.x * a.z; acc[4][3] += w1.x * a.w;
            acc[5][0] += w1.y * a.x; acc[5][1] += w1.y * a.y; acc[5][2] += w1.y * a.z; acc[5][3] += w1.y * a.w;
            acc[6][0] += w1.z * a.x; acc[6][1] += w1.z * a.y; acc[6][2] += w1.z * a.z; acc[6][3] += w1.z * a.w;
            acc[7][0] += w1.w * a.x; acc[7][1] += w1.w * a.y; acc[7][2] += w1.w * a.z; acc[7][3] += w1.w * a.w;
        }
    }

    const int tloc = ng >> 3;
    const int b4   = (ng & 7) * 4;
    float* Crow = &C[(size_t)(t0 + tloc) * N * BB + b4];
#pragma unroll
    for (int ji = 0; ji < 8; ji++) {
        int j = j0 + jg * 8 + ji;
        float bb = bias1 ? bias1[j] : 0.0f;
        if (bias2) bb += bias2[j];
        float4 o = make_float4(acc[ji][0] + bb, acc[ji][1] + bb, acc[ji][2] + bb, acc[ji][3] + bb);
        *(float4*)&Crow[(size_t)j * BB] = o;
    }
}

// ---------------- packed f32x2 helpers ----------------
union F2U { unsigned long long u; float2 f; };

__device__ __forceinline__ void pack2(F2U& d, float lo, float hi) {
    asm("mov.b64 %0, {%1, %2};" : "=l"(d.u) : "f"(lo), "f"(hi));
}
__device__ __forceinline__ void fma2(F2U& a, const F2U& x, const F2U& y) {
    asm("fma.rn.f32x2 %0, %1, %2, %0;" : "+l"(a.u) : "l"(x.u), "l"(y.u));
}

// ---------------- persistent recurrence layer ----------------
// grid: 128 CTAs (co-resident), block: 128 threads. CTA owns 4 hidden columns.
// h buffers [H][B]. Barrier: R6-proven (threadfence + atomicAdd-return +
// volatile spin + nanosleep). Inner loop: packed fma.rn.f32x2 (FFMA2).
__global__ void __launch_bounds__(128)
rnn_layer_kernel(const float* __restrict__ pre, float* __restrict__ traj,
                 const float* __restrict__ W,
                 float* buf0, float* buf1, unsigned* counters)
{
    __shared__ float Wt[16][32][4];   // [kk][kseg][jj]  8KB
    __shared__ float ps[32][132];     // partials [kseg][out], padded

    const int tid  = threadIdx.x;
    const int j0   = blockIdx.x * 4;
    const int bg   = tid & 3;
    const int kseg = tid >> 2;        // 0..31
    const int b0   = bg * 8;

    // preload W slice: Wt[kk][ks][jj] = W[(j0+jj)*H + ks*16 + kk]
    for (int e = tid; e < 2048; e += 128) {
        int jj = e & 3;
        int ks = (e >> 2) & 31;
        int kk = e >> 7;
        Wt[kk][ks][jj] = W[(size_t)(j0 + jj) * HH + ks * 16 + kk];
    }
    __syncthreads();

    const int out_b  = tid >> 2;      // output this thread finalizes
    const int out_jj = tid & 3;
    const size_t pre_off = (size_t)(j0 + out_jj) * BB + out_b;

    float preval = __ldcg(pre + pre_off);   // pre for t=0

    for (int t = 0; t < TT; t++) {
        const float* hb = (t & 1) ? buf1 : buf0;
        float*       hn = (t & 1) ? buf0 : buf1;

        // acc2[p][j]: packed pair over b = (b0+2p, b0+2p+1), column j
        F2U acc2[4][4];
#pragma unroll
        for (int p = 0; p < 4; p++)
#pragma unroll
            for (int j = 0; j < 4; j++) acc2[p][j].u = 0ull;

#pragma unroll
        for (int kk = 0; kk < 16; kk++) {
            const int k = kseg * 16 + kk;
            const float4 w  = *(const float4*)&Wt[kk][kseg][0];
            F2U wp[4];
            pack2(wp[0], w.x, w.x);
            pack2(wp[1], w.y, w.y);
            pack2(wp[2], w.z, w.z);
            pack2(wp[3], w.w, w.w);
            const float4 hA = __ldcg((const float4*)(hb + (k << 5) + b0));
            const float4 hB = __ldcg((const float4*)(hb + (k << 5) + b0 + 4));
            F2U hp[4];
            pack2(hp[0], hA.x, hA.y);
            pack2(hp[1], hA.z, hA.w);
            pack2(hp[2], hB.x, hB.y);
            pack2(hp[3], hB.z, hB.w);
#pragma unroll
            for (int p = 0; p < 4; p++) {
                fma2(acc2[p][0], hp[p], wp[0]);
                fma2(acc2[p][1], hp[p], wp[1]);
                fma2(acc2[p][2], hp[p], wp[2]);
                fma2(acc2[p][3], hp[p], wp[3]);
            }
        }

        // prefetch next step's pre value (independent of h) to hide L2 latency
        float pnext = preval;
        if (t + 1 < TT) pnext = __ldcg(pre + (size_t)(t + 1) * (HH * BB) + pre_off);

        // dump partials: out index = b*4 + jj ; pair p covers b = b0+2p, b0+2p+1
#pragma unroll
        for (int p = 0; p < 4; p++) {
            *(float4*)&ps[kseg][(b0 + 2 * p) * 4] =
                make_float4(acc2[p][0].f.x, acc2[p][1].f.x, acc2[p][2].f.x, acc2[p][3].f.x);
            *(float4*)&ps[kseg][(b0 + 2 * p + 1) * 4] =
                make_float4(acc2[p][0].f.y, acc2[p][1].f.y, acc2[p][2].f.y, acc2[p][3].f.y);
        }
        __syncthreads();

        // reduce 32 k-segments for output 'tid' (4-way split chains)
        float s0 = 0.f, s1 = 0.f, s2 = 0.f, s3 = 0.f;
#pragma unroll
        for (int ss = 0; ss < 32; ss += 4) {
            s0 += ps[ss + 0][tid];
            s1 += ps[ss + 1][tid];
            s2 += ps[ss + 2][tid];
            s3 += ps[ss + 3][tid];
        }
        const float val = tanhf(preval + (s0 + s1) + (s2 + s3));
        const int jdx = j0 + out_jj;
        hn[(size_t)jdx * BB + out_b] = val;
        traj[(size_t)t * (HH * BB) + (size_t)jdx * BB + out_b] = val;

        __threadfence();
        __syncthreads();   // all stores + fences done; also guards ps reuse

        if (tid == 0) {
            unsigned arrived = atomicAdd(&counters[t], 1u) + 1u;
            if (arrived < 128u) {
                volatile unsigned* p = &counters[t];
                while (*p < 128u) { __nanosleep(40); }
            }
        }
        __syncthreads();

        preval = pnext;
    }
}

// ---------------- transpose: g_tmp [T][O][B] -> out [B][O][T] ----------------
__global__ void transpose_kernel(const float* __restrict__ tmp, float* __restrict__ out)
{
    __shared__ float s[32][33];
    const int t0 = blockIdx.x * 32;
    const int o  = blockIdx.y;
    const int tx = threadIdx.x;   // 32
    const int ty = threadIdx.y;   // 8
#pragma unroll
    for (int i = 0; i < 4; i++) {
        int tt = t0 + ty + i * 8;
        s[ty + i * 8][tx] = tmp[(size_t)tt * (OO * BB) + (size_t)o * BB + tx];
    }
    __syncthreads();
#pragma unroll
    for (int i = 0; i < 4; i++) {
        int b = ty + i * 8;
        out[(size_t)b * (OO * TT) + (size_t)o * TT + t0 + tx] = s[tx][b];
    }
}

// ---------------- launch ----------------
extern "C" void kernel_launch(void* const* d_in, const int* in_sizes, int n_in,
                              void* d_out, int out_size)
{
    const float* inputs = (const float*)d_in[0];
    const float* W_ih0  = (const float*)d_in[1];
    const float* W_hh0  = (const float*)d_in[2];
    const float* b_ih0  = (const float*)d_in[3];
    const float* b_hh0  = (const float*)d_in[4];
    const float* W_ih1  = (const float*)d_in[5];
    const float* W_hh1  = (const float*)d_in[6];
    const float* b_ih1  = (const float*)d_in[7];
    const float* b_hh1  = (const float*)d_in[8];
    const float* W_fc   = (const float*)d_in[9];
    const float* b_fc   = (const float*)d_in[10];

    float *pre, *traj, *tmp, *hping;
    unsigned* counters;
    cudaGetSymbolAddress((void**)&pre,      g_pre);
    cudaGetSymbolAddress((void**)&traj,     g_traj);
    cudaGetSymbolAddress((void**)&tmp,      g_tmp);
    cudaGetSymbolAddress((void**)&hping,    g_hping);
    cudaGetSymbolAddress((void**)&counters, g_counters);

    init_kernel<<<64, 256>>>(counters, hping);

    // pre0[t][j][b] = inputs[b][t][:] . W_ih0[j][:] + b_ih0[j] + b_hh0[j]
    gemm_pre_kernel<<<dim3(4, TT / 2), 256>>>(inputs, W_ih0, b_ih0, b_hh0, pre,
                                              II, (long)II, 1L, (long)TT * II, HH);

    // layer 0 recurrence -> h1 trajectory
    rnn_layer_kernel<<<128, 128>>>(pre, traj, W_hh0,
                                   hping, hping + HH * BB, counters);

    // pre1[t][j][b] = h1[t][:][b] . W_ih1[j][:] + b_ih1[j] + b_hh1[j]
    gemm_pre_kernel<<<dim3(4, TT / 2), 256>>>(traj, W_ih1, b_ih1, b_hh1, pre,
                                              HH, (long)HH * BB, (long)BB, 1L, HH);

    // layer 1 recurrence -> h2 trajectory (reuses g_traj)
    rnn_layer_kernel<<<128, 128>>>(pre, traj, W_hh1,
                                   hping + 2 * HH * BB, hping + 3 * HH * BB,
                                   counters + 512);

    // fc: tmp[t][o][b] = h2[t][:][b] . W_fc[o][:] + b_fc[o]
    gemm_pre_kernel<<<dim3(1, TT / 2), 256>>>(traj, W_fc, b_fc, nullptr, tmp,
                                              HH, (long)HH * BB, (long)BB, 1L, OO);

    // out[b][o][t] = tmp[t][o][b]
    transpose_kernel<<<dim3(16, OO), dim3(32, 8)>>>(tmp, (float*)d_out);
}

// round 12
// speedup vs baseline: 1.5903x; 1.5903x over previous
#include <cuda_runtime.h>
#include <math.h>
#include <stdint.h>

// Problem dims
#define BB 32
#define TT 512
#define II 128
#define HH 512
#define OO 128

// ---------------- device scratch (no allocs allowed) ----------------
__device__ float    g_pre [TT * HH * BB];   // [T][H][B] (reused pre0/pre1)
__device__ float    g_traj[TT * HH * BB];   // [T][H][B] (h1, then reused as h2)
__device__ float    g_tmp [TT * OO * BB];   // [T][O][B] (fc pre-transpose)
__device__ float    g_hping[4 * HH * BB];   // 2 ping-pong pairs (layer0, layer1)
__device__ unsigned g_counters[1024];       // per-step barrier counters (512 per layer)

// ---------------- init: zero counters + h0 buffers each replay ----------------
__global__ void init_kernel(unsigned* counters, float* hping) {
    int i = blockIdx.x * blockDim.x + threadIdx.x;
    int stride = gridDim.x * blockDim.x;
    for (int e = i; e < 1024; e += stride) counters[e] = 0u;
    for (int e = i; e < 4 * HH * BB; e += stride) hping[e] = 0.0f;
}

// ---------------- fp32 GEMM: C[t][j][b] = bias(j) + sum_k A(t,k,b)*W[j][k] ----------------
// grid: (N/128, T/2), block: 256. Tile 128j x 64n, microtile 8j x 4n. (R4-proven)
__global__ void __launch_bounds__(256)
gemm_pre_kernel(const float* __restrict__ A, const float* __restrict__ W,
                const float* __restrict__ bias1, const float* __restrict__ bias2,
                float* __restrict__ C,
                int K, long sAt, long sAk, long sAb, int N)
{
    __shared__ float Ws[32][132];  // [k][j] padded (128 j)
    __shared__ float As[32][68];   // [k][n] padded (64 n)

    const int t0  = blockIdx.y * 2;
    const int j0  = blockIdx.x * 128;
    const int tid = threadIdx.x;
    const int jg  = tid >> 4;      // 0..15 (8 j each)
    const int ng  = tid & 15;      // 0..15 (4 n each)

    float acc[8][4];
#pragma unroll
    for (int a = 0; a < 8; a++)
#pragma unroll
        for (int b = 0; b < 4; b++) acc[a][b] = 0.0f;

    for (int kt = 0; kt < K; kt += 32) {
        __syncthreads();
        {
            const int rowb = tid >> 3;
            const int k4   = (tid & 7) * 4;
#pragma unroll
            for (int i = 0; i < 4; i++) {
                const int row = i * 32 + rowb;
                float4 v = *(const float4*)&W[(size_t)(j0 + row) * K + kt + k4];
                Ws[k4 + 0][row] = v.x;
                Ws[k4 + 1][row] = v.y;
                Ws[k4 + 2][row] = v.z;
                Ws[k4 + 3][row] = v.w;
            }
        }
        if (sAb == 1) {   // b-contiguous (trajectory layout [t][k][b])
#pragma unroll
            for (int i = 0; i < 2; i++) {
                int f = tid + i * 256;
                int k  = f >> 4;
                int nq = (f & 15) * 4;
                int tloc = nq >> 5, b4 = nq & 31;
                float4 v = *(const float4*)&A[(size_t)(t0 + tloc) * sAt +
                                              (size_t)(kt + k) * sAk + b4];
                *(float4*)&As[k][nq] = v;
            }
        } else {          // k-contiguous (inputs layout [b][t][i])
#pragma unroll
            for (int i = 0; i < 2; i++) {
                int f = tid + i * 256;
                int n  = f >> 3;
                int kq = (f & 7) * 4;
                int tloc = n >> 5, b = n & 31;
                float4 v = *(const float4*)&A[(size_t)b * sAb +
                                              (size_t)(t0 + tloc) * sAt + kt + kq];
                As[kq + 0][n] = v.x;
                As[kq + 1][n] = v.y;
                As[kq + 2][n] = v.z;
                As[kq + 3][n] = v.w;
            }
        }
        __syncthreads();
#pragma unroll
        for (int k = 0; k < 32; k++) {
            const float4 w0 = *(const float4*)&Ws[k][jg * 8];
            const float4 w1 = *(const float4*)&Ws[k][jg * 8 + 4];
            const float4 a  = *(const float4*)&As[k][ng * 4];
            acc[0][0] += w0.x * a.x; acc[0][1] += w0.x * a.y; acc[0][2] += w0.x * a.z; acc[0][3] += w0.x * a.w;
            acc[1][0] += w0.y * a.x; acc[1][1] += w0.y * a.y; acc[1][2] += w0.y * a.z; acc[1][3] += w0.y * a.w;
            acc[2][0] += w0.z * a.x; acc[2][1] += w0.z * a.y; acc[2][2] += w0.z * a.z; acc[2][3] += w0.z * a.w;
            acc[3][0] += w0.w * a.x; acc[3][1] += w0.w * a.y; acc[3][2] += w0.w * a.z; acc[3][3] += w0.w * a.w;
            acc[4][0] += w1.x * a.x; acc[4][1] += w1.x * a.y; acc[4][2] += w1.x * a.z; acc[4][3] += w1.x * a.w;
            acc[5][0] += w1.y * a.x; acc[5][1] += w1.y * a.y; acc[5][2] += w1.y * a.z; acc[5][3] += w1.y * a.w;
            acc[6][0] += w1.z * a.x; acc[6][1] += w1.z * a.y; acc[6][2] += w1.z * a.z; acc[6][3] += w1.z * a.w;
            acc[7][0] += w1.w * a.x; acc[7][1] += w1.w * a.y; acc[7][2] += w1.w * a.z; acc[7][3] += w1.w * a.w;
        }
    }

    const int tloc = ng >> 3;
    const int b4   = (ng & 7) * 4;
    float* Crow = &C[(size_t)(t0 + tloc) * N * BB + b4];
#pragma unroll
    for (int ji = 0; ji < 8; ji++) {
        int j = j0 + jg * 8 + ji;
        float bb = bias1 ? bias1[j] : 0.0f;
        if (bias2) bb += bias2[j];
        float4 o = make_float4(acc[ji][0] + bb, acc[ji][1] + bb, acc[ji][2] + bb, acc[ji][3] + bb);
        *(float4*)&Crow[(size_t)j * BB] = o;
    }
}

// ---------------- cp.async helpers ----------------
__device__ __forceinline__ void cpasync16(uint32_t saddr, const void* gaddr) {
    asm volatile("cp.async.cg.shared.global [%0], [%1], 16;" :: "r"(saddr), "l"(gaddr));
}
__device__ __forceinline__ void cpasync_wait_all() {
    asm volatile("cp.async.wait_all;" ::: "memory");
}

// ---------------- persistent recurrence layer ----------------
// grid: 128 CTAs (co-resident), block: 128 threads, 64KB dynamic smem.
// CTA owns 4 hidden columns. Per step: bulk-stage h (64KB) into smem via
// cp.async (MLP=32 -> ~525 cyc instead of per-iteration L2 exposure), compute
// from LDS. Thread's k-set interleaved (k = kk*32 + kseg); h stored SW128-
// swizzled so warp LDS.128 phases are conflict-free. Reduce/tanh/store and
// the R6-proven barrier are unchanged.
__global__ void __launch_bounds__(128)
rnn_layer_kernel(const float* __restrict__ pre, float* __restrict__ traj,
                 const float* __restrict__ W,
                 float* buf0, float* buf1, unsigned* counters)
{
    extern __shared__ float4 hs4[];   // 4096 float4 = 64KB, swizzled [k][c]
    __shared__ float Wt[16][32][4];   // [kk][kseg][jj]  8KB
    __shared__ float ps[32][132];     // partials [kseg][out], padded

    const int tid  = threadIdx.x;
    const int j0   = blockIdx.x * 4;
    const int bg   = tid & 3;
    const int kseg = tid >> 2;        // 0..31
    const uint32_t hs_base = (uint32_t)__cvta_generic_to_shared(hs4);

    // preload W slice, matching the interleaved k map: Wt[kk][ks][jj] = W[(j0+jj)*H + kk*32 + ks]
    for (int e = tid; e < 2048; e += 128) {
        int jj = e & 3;
        int ks = (e >> 2) & 31;
        int kk = e >> 7;
        Wt[kk][ks][jj] = W[(size_t)(j0 + jj) * HH + kk * 32 + ks];
    }
    __syncthreads();

    const int out_b  = tid >> 2;      // output this thread finalizes
    const int out_jj = tid & 3;
    const size_t pre_off = (size_t)(j0 + out_jj) * BB + out_b;

    for (int t = 0; t < TT; t++) {
        const float* hb = (t & 1) ? buf1 : buf0;
        float*       hn = (t & 1) ? buf0 : buf1;

        // ---- bulk-stage h into smem (swizzled), MLP = 32 ----
        {
            const float4* gsrc = (const float4*)hb;   // 4096 units: u = k*8 + c
#pragma unroll
            for (int it = 0; it < 32; it++) {
                int u = tid + it * 128;
                int k = u >> 3, c = u & 7;
                int su = (k << 3) | (c ^ (k & 7));    // SW128 swizzle within 128B row
                cpasync16(hs_base + su * 16, gsrc + u);
            }
        }

        const float preval = __ldcg(pre + (size_t)t * (HH * BB) + pre_off);

        cpasync_wait_all();
        __syncthreads();

        // ---- compute from smem ----
        float acc[8][4];
#pragma unroll
        for (int a = 0; a < 8; a++)
#pragma unroll
            for (int b = 0; b < 4; b++) acc[a][b] = 0.0f;

#pragma unroll
        for (int kk = 0; kk < 16; kk++) {
            const int k = kk * 32 + kseg;             // interleaved k-set
            const float4 w = *(const float4*)&Wt[kk][kseg][0];
            const int e = (bg * 2) ^ (k & 7);         // swizzled unit col for b0..b3
            const float4 hA = hs4[(k << 3) | e];
            const float4 hB = hs4[(k << 3) | (e ^ 1)];
            acc[0][0] += hA.x * w.x; acc[0][1] += hA.x * w.y; acc[0][2] += hA.x * w.z; acc[0][3] += hA.x * w.w;
            acc[1][0] += hA.y * w.x; acc[1][1] += hA.y * w.y; acc[1][2] += hA.y * w.z; acc[1][3] += hA.y * w.w;
            acc[2][0] += hA.z * w.x; acc[2][1] += hA.z * w.y; acc[2][2] += hA.z * w.z; acc[2][3] += hA.z * w.w;
            acc[3][0] += hA.w * w.x; acc[3][1] += hA.w * w.y; acc[3][2] += hA.w * w.z; acc[3][3] += hA.w * w.w;
            acc[4][0] += hB.x * w.x; acc[4][1] += hB.x * w.y; acc[4][2] += hB.x * w.z; acc[4][3] += hB.x * w.w;
            acc[5][0] += hB.y * w.x; acc[5][1] += hB.y * w.y; acc[5][2] += hB.y * w.z; acc[5][3] += hB.y * w.w;
            acc[6][0] += hB.z * w.x; acc[6][1] += hB.z * w.y; acc[6][2] += hB.z * w.z; acc[6][3] += hB.z * w.w;
            acc[7][0] += hB.w * w.x; acc[7][1] += hB.w * w.y; acc[7][2] += hB.w * w.z; acc[7][3] += hB.w * w.w;
        }

        // dump partials: out index = b*4 + jj  (b = bg*8 + bi)
#pragma unroll
        for (int bi = 0; bi < 8; bi++) {
            *(float4*)&ps[kseg][(bg * 8 + bi) * 4] =
                make_float4(acc[bi][0], acc[bi][1], acc[bi][2], acc[bi][3]);
        }
        __syncthreads();

        // reduce 32 k-segments for output 'tid' (4-way split chains)
        float s0 = 0.f, s1 = 0.f, s2 = 0.f, s3 = 0.f;
#pragma unroll
        for (int ss = 0; ss < 32; ss += 4) {
            s0 += ps[ss + 0][tid];
            s1 += ps[ss + 1][tid];
            s2 += ps[ss + 2][tid];
            s3 += ps[ss + 3][tid];
        }
        const float val = tanhf(preval + (s0 + s1) + (s2 + s3));
        const int jdx = j0 + out_jj;
        hn[(size_t)jdx * BB + out_b] = val;
        traj[(size_t)t * (HH * BB) + (size_t)jdx * BB + out_b] = val;

        __threadfence();
        __syncthreads();   // all stores + fences done; also guards ps/hs reuse

        if (tid == 0) {
            unsigned arrived = atomicAdd(&counters[t], 1u) + 1u;
            if (arrived < 128u) {
                volatile unsigned* p = &counters[t];
                while (*p < 128u) { __nanosleep(40); }
            }
        }
        __syncthreads();
    }
}

// ---------------- transpose: g_tmp [T][O][B] -> out [B][O][T] ----------------
__global__ void transpose_kernel(const float* __restrict__ tmp, float* __restrict__ out)
{
    __shared__ float s[32][33];
    const int t0 = blockIdx.x * 32;
    const int o  = blockIdx.y;
    const int tx = threadIdx.x;   // 32
    const int ty = threadIdx.y;   // 8
#pragma unroll
    for (int i = 0; i < 4; i++) {
        int tt = t0 + ty + i * 8;
        s[ty + i * 8][tx] = tmp[(size_t)tt * (OO * BB) + (size_t)o * BB + tx];
    }
    __syncthreads();
#pragma unroll
    for (int i = 0; i < 4; i++) {
        int b = ty + i * 8;
        out[(size_t)b * (OO * TT) + (size_t)o * TT + t0 + tx] = s[tx][b];
    }
}

// ---------------- launch ----------------
extern "C" void kernel_launch(void* const* d_in, const int* in_sizes, int n_in,
                              void* d_out, int out_size)
{
    const float* inputs = (const float*)d_in[0];
    const float* W_ih0  = (const float*)d_in[1];
    const float* W_hh0  = (const float*)d_in[2];
    const float* b_ih0  = (const float*)d_in[3];
    const float* b_hh0  = (const float*)d_in[4];
    const float* W_ih1  = (const float*)d_in[5];
    const float* W_hh1  = (const float*)d_in[6];
    const float* b_ih1  = (const float*)d_in[7];
    const float* b_hh1  = (const float*)d_in[8];
    const float* W_fc   = (const float*)d_in[9];
    const float* b_fc   = (const float*)d_in[10];

    float *pre, *traj, *tmp, *hping;
    unsigned* counters;
    cudaGetSymbolAddress((void**)&pre,      g_pre);
    cudaGetSymbolAddress((void**)&traj,     g_traj);
    cudaGetSymbolAddress((void**)&tmp,      g_tmp);
    cudaGetSymbolAddress((void**)&hping,    g_hping);
    cudaGetSymbolAddress((void**)&counters, g_counters);

    // opt-in to 64KB dynamic smem for the recurrence kernel (idempotent)
    cudaFuncSetAttribute(rnn_layer_kernel,
                         cudaFuncAttributeMaxDynamicSharedMemorySize, 65536);

    init_kernel<<<64, 256>>>(counters, hping);

    // pre0[t][j][b] = inputs[b][t][:] . W_ih0[j][:] + b_ih0[j] + b_hh0[j]
    gemm_pre_kernel<<<dim3(4, TT / 2), 256>>>(inputs, W_ih0, b_ih0, b_hh0, pre,
                                              II, (long)II, 1L, (long)TT * II, HH);

    // layer 0 recurrence -> h1 trajectory
    rnn_layer_kernel<<<128, 128, 65536>>>(pre, traj, W_hh0,
                                          hping, hping + HH * BB, counters);

    // pre1[t][j][b] = h1[t][:][b] . W_ih1[j][:] + b_ih1[j] + b_hh1[j]
    gemm_pre_kernel<<<dim3(4, TT / 2), 256>>>(traj, W_ih1, b_ih1, b_hh1, pre,
                                              HH, (long)HH * BB, (long)BB, 1L, HH);

    // layer 1 recurrence -> h2 trajectory (reuses g_traj)
    rnn_layer_kernel<<<128, 128, 65536>>>(pre, traj, W_hh1,
                                          hping + 2 * HH * BB, hping + 3 * HH * BB,
                                          counters + 512);

    // fc: tmp[t][o][b] = h2[t][:][b] . W_fc[o][:] + b_fc[o]
    gemm_pre_kernel<<<dim3(1, TT / 2), 256>>>(traj, W_fc, b_fc, nullptr, tmp,
                                              HH, (long)HH * BB, (long)BB, 1L, OO);

    // out[b][o][t] = tmp[t][o][b]
    transpose_kernel<<<dim3(16, OO), dim3(32, 8)>>>(tmp, (float*)d_out);
}

// round 13
// speedup vs baseline: 1.6470x; 1.0357x over previous
#include <cuda_runtime.h>
#include <math.h>
#include <stdint.h>

// Problem dims
#define BB 32
#define TT 512
#define II 128
#define HH 512
#define OO 128

// ---------------- device scratch (no allocs allowed) ----------------
__device__ float    g_pre [TT * HH * BB];   // [T][H][B] (reused pre0/pre1)
__device__ float    g_traj[TT * HH * BB];   // [T][H][B] (h1, then reused as h2)
__device__ float    g_tmp [TT * OO * BB];   // [T][O][B] (fc pre-transpose)
__device__ float    g_hping[4 * HH * BB];   // 2 ping-pong pairs (layer0, layer1)
__device__ unsigned g_counters[1024];       // per-step barrier counters (512 per layer)

// ---------------- init: zero counters + h0 buffers each replay ----------------
__global__ void init_kernel(unsigned* counters, float* hping) {
    int i = blockIdx.x * blockDim.x + threadIdx.x;
    int stride = gridDim.x * blockDim.x;
    for (int e = i; e < 1024; e += stride) counters[e] = 0u;
    for (int e = i; e < 4 * HH * BB; e += stride) hping[e] = 0.0f;
}

// ---------------- fp32 GEMM: C[t][j][b] = bias(j) + sum_k A(t,k,b)*W[j][k] ----------------
// grid: (N/128, T/2), block: 256. Tile 128j x 64n, microtile 8j x 4n. (R4-proven)
__global__ void __launch_bounds__(256)
gemm_pre_kernel(const float* __restrict__ A, const float* __restrict__ W,
                const float* __restrict__ bias1, const float* __restrict__ bias2,
                float* __restrict__ C,
                int K, long sAt, long sAk, long sAb, int N)
{
    __shared__ float Ws[32][132];  // [k][j] padded (128 j)
    __shared__ float As[32][68];   // [k][n] padded (64 n)

    const int t0  = blockIdx.y * 2;
    const int j0  = blockIdx.x * 128;
    const int tid = threadIdx.x;
    const int jg  = tid >> 4;      // 0..15 (8 j each)
    const int ng  = tid & 15;      // 0..15 (4 n each)

    float acc[8][4];
#pragma unroll
    for (int a = 0; a < 8; a++)
#pragma unroll
        for (int b = 0; b < 4; b++) acc[a][b] = 0.0f;

    for (int kt = 0; kt < K; kt += 32) {
        __syncthreads();
        {
            const int rowb = tid >> 3;
            const int k4   = (tid & 7) * 4;
#pragma unroll
            for (int i = 0; i < 4; i++) {
                const int row = i * 32 + rowb;
                float4 v = *(const float4*)&W[(size_t)(j0 + row) * K + kt + k4];
                Ws[k4 + 0][row] = v.x;
                Ws[k4 + 1][row] = v.y;
                Ws[k4 + 2][row] = v.z;
                Ws[k4 + 3][row] = v.w;
            }
        }
        if (sAb == 1) {   // b-contiguous (trajectory layout [t][k][b])
#pragma unroll
            for (int i = 0; i < 2; i++) {
                int f = tid + i * 256;
                int k  = f >> 4;
                int nq = (f & 15) * 4;
                int tloc = nq >> 5, b4 = nq & 31;
                float4 v = *(const float4*)&A[(size_t)(t0 + tloc) * sAt +
                                              (size_t)(kt + k) * sAk + b4];
                *(float4*)&As[k][nq] = v;
            }
        } else {          // k-contiguous (inputs layout [b][t][i])
#pragma unroll
            for (int i = 0; i < 2; i++) {
                int f = tid + i * 256;
                int n  = f >> 3;
                int kq = (f & 7) * 4;
                int tloc = n >> 5, b = n & 31;
                float4 v = *(const float4*)&A[(size_t)b * sAb +
                                              (size_t)(t0 + tloc) * sAt + kt + kq];
                As[kq + 0][n] = v.x;
                As[kq + 1][n] = v.y;
                As[kq + 2][n] = v.z;
                As[kq + 3][n] = v.w;
            }
        }
        __syncthreads();
#pragma unroll
        for (int k = 0; k < 32; k++) {
            const float4 w0 = *(const float4*)&Ws[k][jg * 8];
            const float4 w1 = *(const float4*)&Ws[k][jg * 8 + 4];
            const float4 a  = *(const float4*)&As[k][ng * 4];
            acc[0][0] += w0.x * a.x; acc[0][1] += w0.x * a.y; acc[0][2] += w0.x * a.z; acc[0][3] += w0.x * a.w;
            acc[1][0] += w0.y * a.x; acc[1][1] += w0.y * a.y; acc[1][2] += w0.y * a.z; acc[1][3] += w0.y * a.w;
            acc[2][0] += w0.z * a.x; acc[2][1] += w0.z * a.y; acc[2][2] += w0.z * a.z; acc[2][3] += w0.z * a.w;
            acc[3][0] += w0.w * a.x; acc[3][1] += w0.w * a.y; acc[3][2] += w0.w * a.z; acc[3][3] += w0.w * a.w;
            acc[4][0] += w1.x * a.x; acc[4][1] += w1.x * a.y; acc[4][2] += w1.x * a.z; acc[4][3] += w1.x * a.w;
            acc[5][0] += w1.y * a.x; acc[5][1] += w1.y * a.y; acc[5][2] += w1.y * a.z; acc[5][3] += w1.y * a.w;
            acc[6][0] += w1.z * a.x; acc[6][1] += w1.z * a.y; acc[6][2] += w1.z * a.z; acc[6][3] += w1.z * a.w;
            acc[7][0] += w1.w * a.x; acc[7][1] += w1.w * a.y; acc[7][2] += w1.w * a.z; acc[7][3] += w1.w * a.w;
        }
    }

    const int tloc = ng >> 3;
    const int b4   = (ng & 7) * 4;
    float* Crow = &C[(size_t)(t0 + tloc) * N * BB + b4];
#pragma unroll
    for (int ji = 0; ji < 8; ji++) {
        int j = j0 + jg * 8 + ji;
        float bb = bias1 ? bias1[j] : 0.0f;
        if (bias2) bb += bias2[j];
        float4 o = make_float4(acc[ji][0] + bb, acc[ji][1] + bb, acc[ji][2] + bb, acc[ji][3] + bb);
        *(float4*)&Crow[(size_t)j * BB] = o;
    }
}

// ---------------- cp.async helpers ----------------
__device__ __forceinline__ void cpasync16(uint32_t saddr, const void* gaddr) {
    asm volatile("cp.async.cg.shared.global [%0], [%1], 16;" :: "r"(saddr), "l"(gaddr));
}
__device__ __forceinline__ void cpasync_commit() {
    asm volatile("cp.async.commit_group;" ::: "memory");
}
template <int N>
__device__ __forceinline__ void cpasync_wait_group() {
    asm volatile("cp.async.wait_group %0;" :: "n"(N) : "memory");
}

// ---------------- persistent recurrence layer ----------------
// grid: 128 CTAs (co-resident), block: 128 threads, 64KB dynamic smem.
// CTA owns 4 hidden columns. Per step: stage h (64KB) into smem via cp.async
// in TWO k-half commit groups; compute on half A (kk 0..7) while half B is
// still in flight, then wait and compute half B. Thread's k-set interleaved
// (k = kk*32 + kseg); h stored SW128-swizzled. Reduce/tanh/store and the
// R6-proven barrier are unchanged.
__global__ void __launch_bounds__(128)
rnn_layer_kernel(const float* __restrict__ pre, float* __restrict__ traj,
                 const float* __restrict__ W,
                 float* buf0, float* buf1, unsigned* counters)
{
    extern __shared__ float4 hs4[];   // 4096 float4 = 64KB, swizzled [k][c]
    __shared__ float Wt[16][32][4];   // [kk][kseg][jj]  8KB
    __shared__ float ps[32][132];     // partials [kseg][out], padded

    const int tid  = threadIdx.x;
    const int j0   = blockIdx.x * 4;
    const int bg   = tid & 3;
    const int kseg = tid >> 2;        // 0..31
    const uint32_t hs_base = (uint32_t)__cvta_generic_to_shared(hs4);

    // preload W slice, matching the interleaved k map: Wt[kk][ks][jj] = W[(j0+jj)*H + kk*32 + ks]
    for (int e = tid; e < 2048; e += 128) {
        int jj = e & 3;
        int ks = (e >> 2) & 31;
        int kk = e >> 7;
        Wt[kk][ks][jj] = W[(size_t)(j0 + jj) * HH + kk * 32 + ks];
    }
    __syncthreads();

    const int out_b  = tid >> 2;      // output this thread finalizes
    const int out_jj = tid & 3;
    const size_t pre_off = (size_t)(j0 + out_jj) * BB + out_b;

    for (int t = 0; t < TT; t++) {
        const float* hb = (t & 1) ? buf1 : buf0;
        float*       hn = (t & 1) ? buf0 : buf1;

        // ---- stage h into smem (swizzled) in two k-half groups ----
        const float4* gsrc = (const float4*)hb;   // 4096 units: u = k*8 + c
        // group A: k 0..255 (it 0..15)
#pragma unroll
        for (int it = 0; it < 16; it++) {
            int u = tid + it * 128;
            int k = u >> 3, c = u & 7;
            int su = (k << 3) | (c ^ (k & 7));    // SW128 swizzle within 128B row
            cpasync16(hs_base + su * 16, gsrc + u);
        }
        cpasync_commit();
        // group B: k 256..511 (it 16..31)
#pragma unroll
        for (int it = 16; it < 32; it++) {
            int u = tid + it * 128;
            int k = u >> 3, c = u & 7;
            int su = (k << 3) | (c ^ (k & 7));
            cpasync16(hs_base + su * 16, gsrc + u);
        }
        cpasync_commit();

        const float preval = __ldcg(pre + (size_t)t * (HH * BB) + pre_off);

        float acc[8][4];
#pragma unroll
        for (int a = 0; a < 8; a++)
#pragma unroll
            for (int b = 0; b < 4; b++) acc[a][b] = 0.0f;

        // ---- wait half A, compute kk 0..7 while half B lands ----
        cpasync_wait_group<1>();
        __syncthreads();
#pragma unroll
        for (int kk = 0; kk < 8; kk++) {
            const int k = kk * 32 + kseg;             // interleaved k-set (k < 256)
            const float4 w = *(const float4*)&Wt[kk][kseg][0];
            const int e = (bg * 2) ^ (k & 7);
            const float4 hA = hs4[(k << 3) | e];
            const float4 hB = hs4[(k << 3) | (e ^ 1)];
            acc[0][0] += hA.x * w.x; acc[0][1] += hA.x * w.y; acc[0][2] += hA.x * w.z; acc[0][3] += hA.x * w.w;
            acc[1][0] += hA.y * w.x; acc[1][1] += hA.y * w.y; acc[1][2] += hA.y * w.z; acc[1][3] += hA.y * w.w;
            acc[2][0] += hA.z * w.x; acc[2][1] += hA.z * w.y; acc[2][2] += hA.z * w.z; acc[2][3] += hA.z * w.w;
            acc[3][0] += hA.w * w.x; acc[3][1] += hA.w * w.y; acc[3][2] += hA.w * w.z; acc[3][3] += hA.w * w.w;
            acc[4][0] += hB.x * w.x; acc[4][1] += hB.x * w.y; acc[4][2] += hB.x * w.z; acc[4][3] += hB.x * w.w;
            acc[5][0] += hB.y * w.x; acc[5][1] += hB.y * w.y; acc[5][2] += hB.y * w.z; acc[5][3] += hB.y * w.w;
            acc[6][0] += hB.z * w.x; acc[6][1] += hB.z * w.y; acc[6][2] += hB.z * w.z; acc[6][3] += hB.z * w.w;
            acc[7][0] += hB.w * w.x; acc[7][1] += hB.w * w.y; acc[7][2] += hB.w * w.z; acc[7][3] += hB.w * w.w;
        }

        // ---- wait half B, compute kk 8..15 ----
        cpasync_wait_group<0>();
        __syncthreads();
#pragma unroll
        for (int kk = 8; kk < 16; kk++) {
            const int k = kk * 32 + kseg;             // k >= 256
            const float4 w = *(const float4*)&Wt[kk][kseg][0];
            const int e = (bg * 2) ^ (k & 7);
            const float4 hA = hs4[(k << 3) | e];
            const float4 hB = hs4[(k << 3) | (e ^ 1)];
            acc[0][0] += hA.x * w.x; acc[0][1] += hA.x * w.y; acc[0][2] += hA.x * w.z; acc[0][3] += hA.x * w.w;
            acc[1][0] += hA.y * w.x; acc[1][1] += hA.y * w.y; acc[1][2] += hA.y * w.z; acc[1][3] += hA.y * w.w;
            acc[2][0] += hA.z * w.x; acc[2][1] += hA.z * w.y; acc[2][2] += hA.z * w.z; acc[2][3] += hA.z * w.w;
            acc[3][0] += hA.w * w.x; acc[3][1] += hA.w * w.y; acc[3][2] += hA.w * w.z; acc[3][3] += hA.w * w.w;
            acc[4][0] += hB.x * w.x; acc[4][1] += hB.x * w.y; acc[4][2] += hB.x * w.z; acc[4][3] += hB.x * w.w;
            acc[5][0] += hB.y * w.x; acc[5][1] += hB.y * w.y; acc[5][2] += hB.y * w.z; acc[5][3] += hB.y * w.w;
            acc[6][0] += hB.z * w.x; acc[6][1] += hB.z * w.y; acc[6][2] += hB.z * w.z; acc[6][3] += hB.z * w.w;
            acc[7][0] += hB.w * w.x; acc[7][1] += hB.w * w.y; acc[7][2] += hB.w * w.z; acc[7][3] += hB.w * w.w;
        }

        // dump partials: out index = b*4 + jj  (b = bg*8 + bi)
#pragma unroll
        for (int bi = 0; bi < 8; bi++) {
            *(float4*)&ps[kseg][(bg * 8 + bi) * 4] =
                make_float4(acc[bi][0], acc[bi][1], acc[bi][2], acc[bi][3]);
        }
        __syncthreads();

        // reduce 32 k-segments for output 'tid' (4-way split chains)
        float s0 = 0.f, s1 = 0.f, s2 = 0.f, s3 = 0.f;
#pragma unroll
        for (int ss = 0; ss < 32; ss += 4) {
            s0 += ps[ss + 0][tid];
            s1 += ps[ss + 1][tid];
            s2 += ps[ss + 2][tid];
            s3 += ps[ss + 3][tid];
        }
        const float val = tanhf(preval + (s0 + s1) + (s2 + s3));
        const int jdx = j0 + out_jj;
        hn[(size_t)jdx * BB + out_b] = val;
        traj[(size_t)t * (HH * BB) + (size_t)jdx * BB + out_b] = val;

        __threadfence();
        __syncthreads();   // all stores + fences done; also guards ps/hs reuse

        if (tid == 0) {
            unsigned arrived = atomicAdd(&counters[t], 1u) + 1u;
            if (arrived < 128u) {
                volatile unsigned* p = &counters[t];
                while (*p < 128u) { __nanosleep(40); }
            }
        }
        __syncthreads();
    }
}

// ---------------- transpose: g_tmp [T][O][B] -> out [B][O][T] ----------------
__global__ void transpose_kernel(const float* __restrict__ tmp, float* __restrict__ out)
{
    __shared__ float s[32][33];
    const int t0 = blockIdx.x * 32;
    const int o  = blockIdx.y;
    const int tx = threadIdx.x;   // 32
    const int ty = threadIdx.y;   // 8
#pragma unroll
    for (int i = 0; i < 4; i++) {
        int tt = t0 + ty + i * 8;
        s[ty + i * 8][tx] = tmp[(size_t)tt * (OO * BB) + (size_t)o * BB + tx];
    }
    __syncthreads();
#pragma unroll
    for (int i = 0; i < 4; i++) {
        int b = ty + i * 8;
        out[(size_t)b * (OO * TT) + (size_t)o * TT + t0 + tx] = s[tx][b];
    }
}

// ---------------- launch ----------------
extern "C" void kernel_launch(void* const* d_in, const int* in_sizes, int n_in,
                              void* d_out, int out_size)
{
    const float* inputs = (const float*)d_in[0];
    const float* W_ih0  = (const float*)d_in[1];
    const float* W_hh0  = (const float*)d_in[2];
    const float* b_ih0  = (const float*)d_in[3];
    const float* b_hh0  = (const float*)d_in[4];
    const float* W_ih1  = (const float*)d_in[5];
    const float* W_hh1  = (const float*)d_in[6];
    const float* b_ih1  = (const float*)d_in[7];
    const float* b_hh1  = (const float*)d_in[8];
    const float* W_fc   = (const float*)d_in[9];
    const float* b_fc   = (const float*)d_in[10];

    float *pre, *traj, *tmp, *hping;
    unsigned* counters;
    cudaGetSymbolAddress((void**)&pre,      g_pre);
    cudaGetSymbolAddress((void**)&traj,     g_traj);
    cudaGetSymbolAddress((void**)&tmp,      g_tmp);
    cudaGetSymbolAddress((void**)&hping,    g_hping);
    cudaGetSymbolAddress((void**)&counters, g_counters);

    // opt-in to 64KB dynamic smem for the recurrence kernel (idempotent)
    cudaFuncSetAttribute(rnn_layer_kernel,
                         cudaFuncAttributeMaxDynamicSharedMemorySize, 65536);

    init_kernel<<<64, 256>>>(counters, hping);

    // pre0[t][j][b] = inputs[b][t][:] . W_ih0[j][:] + b_ih0[j] + b_hh0[j]
    gemm_pre_kernel<<<dim3(4, TT / 2), 256>>>(inputs, W_ih0, b_ih0, b_hh0, pre,
                                              II, (long)II, 1L, (long)TT * II, HH);

    // layer 0 recurrence -> h1 trajectory
    rnn_layer_kernel<<<128, 128, 65536>>>(pre, traj, W_hh0,
                                          hping, hping + HH * BB, counters);

    // pre1[t][j][b] = h1[t][:][b] . W_ih1[j][:] + b_ih1[j] + b_hh1[j]
    gemm_pre_kernel<<<dim3(4, TT / 2), 256>>>(traj, W_ih1, b_ih1, b_hh1, pre,
                                              HH, (long)HH * BB, (long)BB, 1L, HH);

    // layer 1 recurrence -> h2 trajectory (reuses g_traj)
    rnn_layer_kernel<<<128, 128, 65536>>>(pre, traj, W_hh1,
                                          hping + 2 * HH * BB, hping + 3 * HH * BB,
                                          counters + 512);

    // fc: tmp[t][o][b] = h2[t][:][b] . W_fc[o][:] + b_fc[o]
    gemm_pre_kernel<<<dim3(1, TT / 2), 256>>>(traj, W_fc, b_fc, nullptr, tmp,
                                              HH, (long)HH * BB, (long)BB, 1L, OO);

    // out[b][o][t] = tmp[t][o][b]
    transpose_kernel<<<dim3(16, OO), dim3(32, 8)>>>(tmp, (float*)d_out);
}

// round 15
// speedup vs baseline: 2.1953x; 1.3328x over previous
#include <cuda_runtime.h>
#include <math.h>
#include <stdint.h>

// Problem dims
#define BB 32
#define TT 512
#define II 128
#define HH 512
#define OO 128
#define HB (HH * BB)   // 16384 floats per timestep slab

// ---------------- device scratch (no allocs allowed) ----------------
__device__ float    g_pre [TT * HH * BB];          // [T][H][B] pre0
__device__ float    g_h1  [(TT + 1) * HH * BB];    // h1 traj, slot-shifted: h1[t] at slot t+1, slot0 = 0
__device__ float    g_h2  [(TT + 1) * HH * BB];    // h2 traj, slot-shifted
__device__ float    g_tmp [TT * OO * BB];          // [T][O][B] fc pre-transpose
__device__ unsigned g_counters[1024];              // per-fused-step barrier counters (513 used)

// dynamic smem: 8192 float4 (two h slabs, 128KB) + 2*32*132 floats (partials, 33KB)
#define DSMEM_BYTES (131072 + 2 * 32 * 132 * 4)

// ---------------- init: zero counters + zero slot0 each replay ----------------
__global__ void init_kernel(unsigned* counters, float* h1, float* h2) {
    int i = blockIdx.x * blockDim.x + threadIdx.x;
    int stride = gridDim.x * blockDim.x;
    for (int e = i; e < 1024; e += stride) counters[e] = 0u;
    for (int e = i; e < HB; e += stride) { h1[e] = 0.0f; h2[e] = 0.0f; }
}

// ---------------- fp32 GEMM: C[t][j][b] = bias(j) + sum_k A(t,k,b)*W[j][k] ----------------
// grid: (N/128, T/2), block: 256. Tile 128j x 64n, microtile 8j x 4n. (R4-proven)
__global__ void __launch_bounds__(256)
gemm_pre_kernel(const float* __restrict__ A, const float* __restrict__ W,
                const float* __restrict__ bias1, const float* __restrict__ bias2,
                float* __restrict__ C,
                int K, long sAt, long sAk, long sAb, int N)
{
    __shared__ float Ws[32][132];  // [k][j] padded (128 j)
    __shared__ float As[32][68];   // [k][n] padded (64 n)

    const int t0  = blockIdx.y * 2;
    const int j0  = blockIdx.x * 128;
    const int tid = threadIdx.x;
    const int jg  = tid >> 4;      // 0..15 (8 j each)
    const int ng  = tid & 15;      // 0..15 (4 n each)

    float acc[8][4];
#pragma unroll
    for (int a = 0; a < 8; a++)
#pragma unroll
        for (int b = 0; b < 4; b++) acc[a][b] = 0.0f;

    for (int kt = 0; kt < K; kt += 32) {
        __syncthreads();
        {
            const int rowb = tid >> 3;
            const int k4   = (tid & 7) * 4;
#pragma unroll
            for (int i = 0; i < 4; i++) {
                const int row = i * 32 + rowb;
                float4 v = *(const float4*)&W[(size_t)(j0 + row) * K + kt + k4];
                Ws[k4 + 0][row] = v.x;
                Ws[k4 + 1][row] = v.y;
                Ws[k4 + 2][row] = v.z;
                Ws[k4 + 3][row] = v.w;
            }
        }
        if (sAb == 1) {   // b-contiguous (trajectory layout [t][k][b])
#pragma unroll
            for (int i = 0; i < 2; i++) {
                int f = tid + i * 256;
                int k  = f >> 4;
                int nq = (f & 15) * 4;
                int tloc = nq >> 5, b4 = nq & 31;
                float4 v = *(const float4*)&A[(size_t)(t0 + tloc) * sAt +
                                              (size_t)(kt + k) * sAk + b4];
                *(float4*)&As[k][nq] = v;
            }
        } else {          // k-contiguous (inputs layout [b][t][i])
#pragma unroll
            for (int i = 0; i < 2; i++) {
                int f = tid + i * 256;
                int n  = f >> 3;
                int kq = (f & 7) * 4;
                int tloc = n >> 5, b = n & 31;
                float4 v = *(const float4*)&A[(size_t)b * sAb +
                                              (size_t)(t0 + tloc) * sAt + kt + kq];
                As[kq + 0][n] = v.x;
                As[kq + 1][n] = v.y;
                As[kq + 2][n] = v.z;
                As[kq + 3][n] = v.w;
            }
        }
        __syncthreads();
#pragma unroll
        for (int k = 0; k < 32; k++) {
            const float4 w0 = *(const float4*)&Ws[k][jg * 8];
            const float4 w1 = *(const float4*)&Ws[k][jg * 8 + 4];
            const float4 a  = *(const float4*)&As[k][ng * 4];
            acc[0][0] += w0.x * a.x; acc[0][1] += w0.x * a.y; acc[0][2] += w0.x * a.z; acc[0][3] += w0.x * a.w;
            acc[1][0] += w0.y * a.x; acc[1][1] += w0.y * a.y; acc[1][2] += w0.y * a.z; acc[1][3] += w0.y * a.w;
            acc[2][0] += w0.z * a.x; acc[2][1] += w0.z * a.y; acc[2][2] += w0.z * a.z; acc[2][3] += w0.z * a.w;
            acc[3][0] += w0.w * a.x; acc[3][1] += w0.w * a.y; acc[3][2] += w0.w * a.z; acc[3][3] += w0.w * a.w;
            acc[4][0] += w1.x * a.x; acc[4][1] += w1.x * a.y; acc[4][2] += w1.x * a.z; acc[4][3] += w1.x * a.w;
            acc[5][0] += w1.y * a.x; acc[5][1] += w1.y * a.y; acc[5][2] += w1.y * a.z; acc[5][3] += w1.y * a.w;
            acc[6][0] += w1.z * a.x; acc[6][1] += w1.z * a.y; acc[6][2] += w1.z * a.z; acc[6][3] += w1.z * a.w;
            acc[7][0] += w1.w * a.x; acc[7][1] += w1.w * a.y; acc[7][2] += w1.w * a.z; acc[7][3] += w1.w * a.w;
        }
    }

    const int tloc = ng >> 3;
    const int b4   = (ng & 7) * 4;
    float* Crow = &C[(size_t)(t0 + tloc) * N * BB + b4];
#pragma unroll
    for (int ji = 0; ji < 8; ji++) {
        int j = j0 + jg * 8 + ji;
        float bb = bias1 ? bias1[j] : 0.0f;
        if (bias2) bb += bias2[j];
        float4 o = make_float4(acc[ji][0] + bb, acc[ji][1] + bb, acc[ji][2] + bb, acc[ji][3] + bb);
        *(float4*)&Crow[(size_t)j * BB] = o;
    }
}

// ---------------- cp.async helpers ----------------
__device__ __forceinline__ void cpasync16(uint32_t saddr, const void* gaddr) {
    asm volatile("cp.async.cg.shared.global [%0], [%1], 16;" :: "r"(saddr), "l"(gaddr));
}
__device__ __forceinline__ void cpasync_commit() {
    asm volatile("cp.async.commit_group;" ::: "memory");
}
template <int N>
__device__ __forceinline__ void cpasync_wait_group() {
    asm volatile("cp.async.wait_group %0;" :: "n"(N) : "memory");
}

// ---------------- fused two-layer wavefront recurrence (smem-staged) ----------------
// grid: 128 CTAs, block: 128 threads, ~161KB dynamic smem (two h slabs + partials).
// Fused step s: stage h1[s-1] and h2[s-2] slabs via cp.async (4 commit groups,
// pipelined against the 3 GEMM slices), compute h1[s] = tanh(pre0 + W_hh0 h1)
// and h2[s-1] = tanh(bias1 + W_ih1 h1 + W_hh1 h2). 513 barriers vs 1024.
// Barrier = R6-proven flat pattern.
__global__ void __launch_bounds__(128)
fused_rnn_kernel(const float* __restrict__ pre,
                 float* __restrict__ h1traj, float* __restrict__ h2traj,
                 const float* __restrict__ Whh0,
                 const float* __restrict__ Wih1, const float* __restrict__ Whh1,
                 const float* __restrict__ b_ih1, const float* __restrict__ b_hh1,
                 unsigned* counters)
{
    extern __shared__ float4 hs[];     // [0:4096) h1 slab, [4096:8192) h2 slab (swizzled), then ps0/ps1
    __shared__ float Wt0 [16][32][4];  // W_hh0 slice  8KB   (k = kk*32 + kseg)
    __shared__ float Wt1i[16][32][4];  // W_ih1 slice  8KB
    __shared__ float Wt1h[16][32][4];  // W_hh1 slice  8KB

    const int tid  = threadIdx.x;
    const int j0   = blockIdx.x * 4;
    const int bg   = tid & 3;
    const int kseg = tid >> 2;         // 0..31
    const uint32_t hs_base = (uint32_t)__cvta_generic_to_shared(hs);
    float4* const hs1 = hs;
    float4* const hs2 = hs + 4096;
    float* const ps0 = (float*)(hs + 8192);        // [32][132]
    float* const ps1 = ps0 + 32 * 132;             // [32][132]

    // preload W slices with interleaved k map: Wt[kk][ks][jj] = W[(j0+jj)*H + kk*32 + ks]
    for (int e = tid; e < 2048; e += 128) {
        int jj = e & 3;
        int ks = (e >> 2) & 31;
        int kk = e >> 7;
        size_t widx = (size_t)(j0 + jj) * HH + kk * 32 + ks;
        Wt0 [kk][ks][jj] = Whh0[widx];
        Wt1i[kk][ks][jj] = Wih1[widx];
        Wt1h[kk][ks][jj] = Whh1[widx];
    }
    __syncthreads();

    const int out_b  = tid >> 2;
    const int out_jj = tid & 3;
    const int jdx    = j0 + out_jj;
    const size_t pre_off = (size_t)jdx * BB + out_b;
    const float bias1v = b_ih1[jdx] + b_hh1[jdx];

    for (int s = 0; s <= TT; s++) {
        const bool l0 = (s < TT);                    // layer0 computes h1[s]
        const bool l1 = (s >= 1);                    // layer1 computes h2[s-1]
        const int  tp = l0 ? s : (TT - 1);           // clamped pre0 step
        const int  h2slot = l1 ? (s - 1) : 0;        // h2[s-2] slot (slot0 = zeros)

        const float4* g1 = (const float4*)(h1traj + (size_t)s * HB);
        const float4* g2 = (const float4*)(h2traj + (size_t)h2slot * HB);

        // ---- issue staging: 4 commit groups (h1 A, h1 B, h2 A, h2 B) ----
#pragma unroll
        for (int it = 0; it < 16; it++) {
            int u = tid + it * 128;
            int k = u >> 3, c = u & 7;
            int su = (k << 3) | (c ^ (k & 7));
            cpasync16(hs_base + su * 16, g1 + u);
        }
        cpasync_commit();
#pragma unroll
        for (int it = 16; it < 32; it++) {
            int u = tid + it * 128;
            int k = u >> 3, c = u & 7;
            int su = (k << 3) | (c ^ (k & 7));
            cpasync16(hs_base + su * 16, g1 + u);
        }
        cpasync_commit();
#pragma unroll
        for (int it = 0; it < 16; it++) {
            int u = tid + it * 128;
            int k = u >> 3, c = u & 7;
            int su = (k << 3) | (c ^ (k & 7));
            cpasync16(hs_base + 65536 + su * 16, g2 + u);
        }
        cpasync_commit();
#pragma unroll
        for (int it = 16; it < 32; it++) {
            int u = tid + it * 128;
            int k = u >> 3, c = u & 7;
            int su = (k << 3) | (c ^ (k & 7));
            cpasync16(hs_base + 65536 + su * 16, g2 + u);
        }
        cpasync_commit();

        const float preval = __ldcg(pre + (size_t)tp * HB + pre_off);

        float acc0[8][4], acc1[8][4];
#pragma unroll
        for (int a = 0; a < 8; a++)
#pragma unroll
            for (int b = 0; b < 4; b++) { acc0[a][b] = 0.0f; acc1[a][b] = 0.0f; }

        const int eb = bg * 2;   // base unit col pair for this thread's 8 b

        // ---- h1 half A: kk 0..7 -> acc0 (Whh0) and acc1 (Wih1) ----
        cpasync_wait_group<3>();
        __syncthreads();
#pragma unroll
        for (int kk = 0; kk < 8; kk++) {
            const int k = kk * 32 + kseg;
            const int e = eb ^ (k & 7);
            const float4 hA = hs1[(k << 3) | e];
            const float4 hB = hs1[(k << 3) | (e ^ 1)];
            const float4 w0 = *(const float4*)&Wt0 [kk][kseg][0];
            const float4 wi = *(const float4*)&Wt1i[kk][kseg][0];
            acc0[0][0] += hA.x * w0.x; acc0[0][1] += hA.x * w0.y; acc0[0][2] += hA.x * w0.z; acc0[0][3] += hA.x * w0.w;
            acc0[1][0] += hA.y * w0.x; acc0[1][1] += hA.y * w0.y; acc0[1][2] += hA.y * w0.z; acc0[1][3] += hA.y * w0.w;
            acc0[2][0] += hA.z * w0.x; acc0[2][1] += hA.z * w0.y; acc0[2][2] += hA.z * w0.z; acc0[2][3] += hA.z * w0.w;
            acc0[3][0] += hA.w * w0.x; acc0[3][1] += hA.w * w0.y; acc0[3][2] += hA.w * w0.z; acc0[3][3] += hA.w * w0.w;
            acc0[4][0] += hB.x * w0.x; acc0[4][1] += hB.x * w0.y; acc0[4][2] += hB.x * w0.z; acc0[4][3] += hB.x * w0.w;
            acc0[5][0] += hB.y * w0.x; acc0[5][1] += hB.y * w0.y; acc0[5][2] += hB.y * w0.z; acc0[5][3] += hB.y * w0.w;
            acc0[6][0] += hB.z * w0.x; acc0[6][1] += hB.z * w0.y; acc0[6][2] += hB.z * w0.z; acc0[6][3] += hB.z * w0.w;
            acc0[7][0] += hB.w * w0.x; acc0[7][1] += hB.w * w0.y; acc0[7][2] += hB.w * w0.z; acc0[7][3] += hB.w * w0.w;
            acc1[0][0] += hA.x * wi.x; acc1[0][1] += hA.x * wi.y; acc1[0][2] += hA.x * wi.z; acc1[0][3] += hA.x * wi.w;
            acc1[1][0] += hA.y * wi.x; acc1[1][1] += hA.y * wi.y; acc1[1][2] += hA.y * wi.z; acc1[1][3] += hA.y * wi.w;
            acc1[2][0] += hA.z * wi.x; acc1[2][1] += hA.z * wi.y; acc1[2][2] += hA.z * wi.z; acc1[2][3] += hA.z * wi.w;
            acc1[3][0] += hA.w * wi.x; acc1[3][1] += hA.w * wi.y; acc1[3][2] += hA.w * wi.z; acc1[3][3] += hA.w * wi.w;
            acc1[4][0] += hB.x * wi.x; acc1[4][1] += hB.x * wi.y; acc1[4][2] += hB.x * wi.z; acc1[4][3] += hB.x * wi.w;
            acc1[5][0] += hB.y * wi.x; acc1[5][1] += hB.y * wi.y; acc1[5][2] += hB.y * wi.z; acc1[5][3] += hB.y * wi.w;
            acc1[6][0] += hB.z * wi.x; acc1[6][1] += hB.z * wi.y; acc1[6][2] += hB.z * wi.z; acc1[6][3] += hB.z * wi.w;
            acc1[7][0] += hB.w * wi.x; acc1[7][1] += hB.w * wi.y; acc1[7][2] += hB.w * wi.z; acc1[7][3] += hB.w * wi.w;
        }

        // ---- h1 half B: kk 8..15 ----
        cpasync_wait_group<2>();
        __syncthreads();
#pragma unroll
        for (int kk = 8; kk < 16; kk++) {
            const int k = kk * 32 + kseg;
            const int e = eb ^ (k & 7);
            const float4 hA = hs1[(k << 3) | e];
            const float4 hB = hs1[(k << 3) | (e ^ 1)];
            const float4 w0 = *(const float4*)&Wt0 [kk][kseg][0];
            const float4 wi = *(const float4*)&Wt1i[kk][kseg][0];
            acc0[0][0] += hA.x * w0.x; acc0[0][1] += hA.x * w0.y; acc0[0][2] += hA.x * w0.z; acc0[0][3] += hA.x * w0.w;
            acc0[1][0] += hA.y * w0.x; acc0[1][1] += hA.y * w0.y; acc0[1][2] += hA.y * w0.z; acc0[1][3] += hA.y * w0.w;
            acc0[2][0] += hA.z * w0.x; acc0[2][1] += hA.z * w0.y; acc0[2][2] += hA.z * w0.z; acc0[2][3] += hA.z * w0.w;
            acc0[3][0] += hA.w * w0.x; acc0[3][1] += hA.w * w0.y; acc0[3][2] += hA.w * w0.z; acc0[3][3] += hA.w * w0.w;
            acc0[4][0] += hB.x * w0.x; acc0[4][1] += hB.x * w0.y; acc0[4][2] += hB.x * w0.z; acc0[4][3] += hB.x * w0.w;
            acc0[5][0] += hB.y * w0.x; acc0[5][1] += hB.y * w0.y; acc0[5][2] += hB.y * w0.z; acc0[5][3] += hB.y * w0.w;
            acc0[6][0] += hB.z * w0.x; acc0[6][1] += hB.z * w0.y; acc0[6][2] += hB.z * w0.z; acc0[6][3] += hB.z * w0.w;
            acc0[7][0] += hB.w * w0.x; acc0[7][1] += hB.w * w0.y; acc0[7][2] += hB.w * w0.z; acc0[7][3] += hB.w * w0.w;
            acc1[0][0] += hA.x * wi.x; acc1[0][1] += hA.x * wi.y; acc1[0][2] += hA.x * wi.z; acc1[0][3] += hA.x * wi.w;
            acc1[1][0] += hA.y * wi.x; acc1[1][1] += hA.y * wi.y; acc1[1][2] += hA.y * wi.z; acc1[1][3] += hA.y * wi.w;
            acc1[2][0] += hA.z * wi.x; acc1[2][1] += hA.z * wi.y; acc1[2][2] += hA.z * wi.z; acc1[2][3] += hA.z * wi.w;
            acc1[3][0] += hA.w * wi.x; acc1[3][1] += hA.w * wi.y; acc1[3][2] += hA.w * wi.z; acc1[3][3] += hA.w * wi.w;
            acc1[4][0] += hB.x * wi.x; acc1[4][1] += hB.x * wi.y; acc1[4][2] += hB.x * wi.z; acc1[4][3] += hB.x * wi.w;
            acc1[5][0] += hB.y * wi.x; acc1[5][1] += hB.y * wi.y; acc1[5][2] += hB.y * wi.z; acc1[5][3] += hB.y * wi.w;
            acc1[6][0] += hB.z * wi.x; acc1[6][1] += hB.z * wi.y; acc1[6][2] += hB.z * wi.z; acc1[6][3] += hB.z * wi.w;
            acc1[7][0] += hB.w * wi.x; acc1[7][1] += hB.w * wi.y; acc1[7][2] += hB.w * wi.z; acc1[7][3] += hB.w * wi.w;
        }

        // ---- h2 half A: kk 0..7 -> acc1 (Whh1) ----
        cpasync_wait_group<1>();
        __syncthreads();
#pragma unroll
        for (int kk = 0; kk < 8; kk++) {
            const int k = kk * 32 + kseg;
            const int e = eb ^ (k & 7);
            const float4 hA = hs2[(k << 3) | e];
            const float4 hB = hs2[(k << 3) | (e ^ 1)];
            const float4 wh = *(const float4*)&Wt1h[kk][kseg][0];
            acc1[0][0] += hA.x * wh.x; acc1[0][1] += hA.x * wh.y; acc1[0][2] += hA.x * wh.z; acc1[0][3] += hA.x * wh.w;
            acc1[1][0] += hA.y * wh.x; acc1[1][1] += hA.y * wh.y; acc1[1][2] += hA.y * wh.z; acc1[1][3] += hA.y * wh.w;
            acc1[2][0] += hA.z * wh.x; acc1[2][1] += hA.z * wh.y; acc1[2][2] += hA.z * wh.z; acc1[2][3] += hA.z * wh.w;
            acc1[3][0] += hA.w * wh.x; acc1[3][1] += hA.w * wh.y; acc1[3][2] += hA.w * wh.z; acc1[3][3] += hA.w * wh.w;
            acc1[4][0] += hB.x * wh.x; acc1[4][1] += hB.x * wh.y; acc1[4][2] += hB.x * wh.z; acc1[4][3] += hB.x * wh.w;
            acc1[5][0] += hB.y * wh.x; acc1[5][1] += hB.y * wh.y; acc1[5][2] += hB.y * wh.z; acc1[5][3] += hB.y * wh.w;
            acc1[6][0] += hB.z * wh.x; acc1[6][1] += hB.z * wh.y; acc1[6][2] += hB.z * wh.z; acc1[6][3] += hB.z * wh.w;
            acc1[7][0] += hB.w * wh.x; acc1[7][1] += hB.w * wh.y; acc1[7][2] += hB.w * wh.z; acc1[7][3] += hB.w * wh.w;
        }

        // ---- h2 half B: kk 8..15 ----
        cpasync_wait_group<0>();
        __syncthreads();
#pragma unroll
        for (int kk = 8; kk < 16; kk++) {
            const int k = kk * 32 + kseg;
            const int e = eb ^ (k & 7);
            const float4 hA = hs2[(k << 3) | e];
            const float4 hB = hs2[(k << 3) | (e ^ 1)];
            const float4 wh = *(const float4*)&Wt1h[kk][kseg][0];
            acc1[0][0] += hA.x * wh.x; acc1[0][1] += hA.x * wh.y; acc1[0][2] += hA.x * wh.z; acc1[0][3] += hA.x * wh.w;
            acc1[1][0] += hA.y * wh.x; acc1[1][1] += hA.y * wh.y; acc1[1][2] += hA.y * wh.z; acc1[1][3] += hA.y * wh.w;
            acc1[2][0] += hA.z * wh.x; acc1[2][1] += hA.z * wh.y; acc1[2][2] += hA.z * wh.z; acc1[2][3] += hA.z * wh.w;
            acc1[3][0] += hA.w * wh.x; acc1[3][1] += hA.w * wh.y; acc1[3][2] += hA.w * wh.z; acc1[3][3] += hA.w * wh.w;
            acc1[4][0] += hB.x * wh.x; acc1[4][1] += hB.x * wh.y; acc1[4][2] += hB.x * wh.z; acc1[4][3] += hB.x * wh.w;
            acc1[5][0] += hB.y * wh.x; acc1[5][1] += hB.y * wh.y; acc1[5][2] += hB.y * wh.z; acc1[5][3] += hB.y * wh.w;
            acc1[6][0] += hB.z * wh.x; acc1[6][1] += hB.z * wh.y; acc1[6][2] += hB.z * wh.z; acc1[6][3] += hB.z * wh.w;
            acc1[7][0] += hB.w * wh.x; acc1[7][1] += hB.w * wh.y; acc1[7][2] += hB.w * wh.z; acc1[7][3] += hB.w * wh.w;
        }

        // ---- dump both partial sets, one sync, both reduces ----
#pragma unroll
        for (int bi = 0; bi < 8; bi++) {
            *(float4*)&ps0[kseg * 132 + (bg * 8 + bi) * 4] =
                make_float4(acc0[bi][0], acc0[bi][1], acc0[bi][2], acc0[bi][3]);
            *(float4*)&ps1[kseg * 132 + (bg * 8 + bi) * 4] =
                make_float4(acc1[bi][0], acc1[bi][1], acc1[bi][2], acc1[bi][3]);
        }
        __syncthreads();

        {
            float a0 = 0.f, a1 = 0.f, a2 = 0.f, a3 = 0.f;
            float c0 = 0.f, c1 = 0.f, c2 = 0.f, c3 = 0.f;
#pragma unroll
            for (int ss = 0; ss < 32; ss += 4) {
                a0 += ps0[(ss + 0) * 132 + tid];
                a1 += ps0[(ss + 1) * 132 + tid];
                a2 += ps0[(ss + 2) * 132 + tid];
                a3 += ps0[(ss + 3) * 132 + tid];
                c0 += ps1[(ss + 0) * 132 + tid];
                c1 += ps1[(ss + 1) * 132 + tid];
                c2 += ps1[(ss + 2) * 132 + tid];
                c3 += ps1[(ss + 3) * 132 + tid];
            }
            if (l0) {
                const float v = tanhf(preval + (a0 + a1) + (a2 + a3));
                h1traj[(size_t)(s + 1) * HB + pre_off] = v;
            }
            if (l1) {
                const float v = tanhf(bias1v + (c0 + c1) + (c2 + c3));
                h2traj[(size_t)s * HB + pre_off] = v;
            }
        }

        // ---- grid barrier (R6-proven flat pattern) ----
        __threadfence();
        __syncthreads();

        if (tid == 0) {
            unsigned arrived = atomicAdd(&counters[s], 1u) + 1u;
            if (arrived < 128u) {
                volatile unsigned* p = &counters[s];
                while (*p < 128u) { __nanosleep(40); }
            }
        }
        __syncthreads();
    }
}

// ---------------- transpose: g_tmp [T][O][B] -> out [B][O][T] ----------------
__global__ void transpose_kernel(const float* __restrict__ tmp, float* __restrict__ out)
{
    __shared__ float s[32][33];
    const int t0 = blockIdx.x * 32;
    const int o  = blockIdx.y;
    const int tx = threadIdx.x;   // 32
    const int ty = threadIdx.y;   // 8
#pragma unroll
    for (int i = 0; i < 4; i++) {
        int tt = t0 + ty + i * 8;
        s[ty + i * 8][tx] = tmp[(size_t)tt * (OO * BB) + (size_t)o * BB + tx];
    }
    __syncthreads();
#pragma unroll
    for (int i = 0; i < 4; i++) {
        int b = ty + i * 8;
        out[(size_t)b * (OO * TT) + (size_t)o * TT + t0 + tx] = s[tx][b];
    }
}

// ---------------- launch ----------------
extern "C" void kernel_launch(void* const* d_in, const int* in_sizes, int n_in,
                              void* d_out, int out_size)
{
    const float* inputs = (const float*)d_in[0];
    const float* W_ih0  = (const float*)d_in[1];
    const float* W_hh0  = (const float*)d_in[2];
    const float* b_ih0  = (const float*)d_in[3];
    const float* b_hh0  = (const float*)d_in[4];
    const float* W_ih1  = (const float*)d_in[5];
    const float* W_hh1  = (const float*)d_in[6];
    const float* b_ih1  = (const float*)d_in[7];
    const float* b_hh1  = (const float*)d_in[8];
    const float* W_fc   = (const float*)d_in[9];
    const float* b_fc   = (const float*)d_in[10];

    float *pre, *h1, *h2, *tmp;
    unsigned* counters;
    cudaGetSymbolAddress((void**)&pre,      g_pre);
    cudaGetSymbolAddress((void**)&h1,       g_h1);
    cudaGetSymbolAddress((void**)&h2,       g_h2);
    cudaGetSymbolAddress((void**)&tmp,      g_tmp);
    cudaGetSymbolAddress((void**)&counters, g_counters);

    // opt-in to large dynamic smem (idempotent)
    cudaFuncSetAttribute(fused_rnn_kernel,
                         cudaFuncAttributeMaxDynamicSharedMemorySize, DSMEM_BYTES);

    init_kernel<<<64, 256>>>(counters, h1, h2);

    // pre0[t][j][b] = inputs[b][t][:] . W_ih0[j][:] + b_ih0[j] + b_hh0[j]
    gemm_pre_kernel<<<dim3(4, TT / 2), 256>>>(inputs, W_ih0, b_ih0, b_hh0, pre,
                                              II, (long)II, 1L, (long)TT * II, HH);

    // fused two-layer wavefront: writes h1 traj (slots 1..T) and h2 traj (slots 1..T)
    fused_rnn_kernel<<<128, 128, DSMEM_BYTES>>>(pre, h1, h2, W_hh0, W_ih1, W_hh1,
                                                b_ih1, b_hh1, counters);

    // fc: tmp[t][o][b] = h2[t][:][b] . W_fc[o][:] + b_fc[o]   (h2[t] at slot t+1)
    gemm_pre_kernel<<<dim3(1, TT / 2), 256>>>(h2 + HB, W_fc, b_fc, nullptr, tmp,
                                              HH, (long)HB, (long)BB, 1L, OO);

    // out[b][o][t] = tmp[t][o][b]
    transpose_kernel<<<dim3(16, OO), dim3(32, 8)>>>(tmp, (float*)d_out);
}